// round 11
// baseline (speedup 1.0000x reference)
#include <cuda_runtime.h>
#include <cstdint>
#include <math_constants.h>

// Problem shape
#define BN   32768   // B*N rows
#define DD   1024    // input dim
#define EE   512     // projection dim
#define CC   4096    // codebook size

#define TM   16      // rows per block

// ONE fused kernel: P = X@W (rows m0..m0+15), then argmax_c dot(P,c)/max(||c||,eps).
// No device globals, no inter-kernel dependencies. Output written as FLOAT
// (indices < 2^24 are exact in fp32).
__global__ __launch_bounds__(256)
void rpq_all(const float* __restrict__ X,
             const float* __restrict__ W,
             const float* __restrict__ CB,
             float* __restrict__ out) {
    __shared__ __align__(16) float Ps[TM][EE + 8];   // 16 x 520 = 33.3 KB
    __shared__ __align__(16) float As[8][TM];        // 0.5 KB
    __shared__ __align__(16) float Ts[8][128];       // 4 KB  (W-tile, then C-tile)
    __shared__ float inv_s[128];                     // per-code inverse norms (tile)

    const int tid = threadIdx.x;          // 256
    const int m0  = blockIdx.x * TM;      // 2048 blocks
    const int tx  = tid & 31;             // 4 cols/codes per thread
    const int ty  = tid >> 5;             // 0..7  (warp id); rows 2ty, 2ty+1
    const int r0  = 2 * ty, r1 = r0 + 1;

    // ============ Phase A: Ps[16][512] = X[16 x 1024] @ W[1024 x 512] ============
    for (int nw = 0; nw < EE / 128; ++nw) {          // 4 chunks of 128 cols
        float acc0[4] = {0.f, 0.f, 0.f, 0.f};
        float acc1[4] = {0.f, 0.f, 0.f, 0.f};

        for (int kt = 0; kt < DD / 8; ++kt) {        // 128 k-tiles of 8
            if (tid < 32) {                          // A tile: 16 rows x 8 k
                const int am = tid >> 1, ak = (tid & 1) * 4;
                float4 v = *reinterpret_cast<const float4*>(
                    X + (size_t)(m0 + am) * DD + kt * 8 + ak);
                As[ak + 0][am] = v.x; As[ak + 1][am] = v.y;
                As[ak + 2][am] = v.z; As[ak + 3][am] = v.w;
            }
            {                                        // W tile: 8 k x 128 cols
                const int bk = tid >> 5, be = (tid & 31) * 4;
                float4 v = *reinterpret_cast<const float4*>(
                    W + (size_t)(kt * 8 + bk) * EE + nw * 128 + be);
                *reinterpret_cast<float4*>(&Ts[bk][be]) = v;
            }
            __syncthreads();

            #pragma unroll
            for (int kk = 0; kk < 8; ++kk) {
                const float a0 = As[kk][r0];
                const float a1 = As[kk][r1];
                float4 b = *reinterpret_cast<const float4*>(&Ts[kk][tx * 4]);
                acc0[0] = fmaf(a0, b.x, acc0[0]); acc0[1] = fmaf(a0, b.y, acc0[1]);
                acc0[2] = fmaf(a0, b.z, acc0[2]); acc0[3] = fmaf(a0, b.w, acc0[3]);
                acc1[0] = fmaf(a1, b.x, acc1[0]); acc1[1] = fmaf(a1, b.y, acc1[1]);
                acc1[2] = fmaf(a1, b.z, acc1[2]); acc1[3] = fmaf(a1, b.w, acc1[3]);
            }
            __syncthreads();
        }
        *reinterpret_cast<float4*>(&Ps[r0][nw * 128 + tx * 4]) =
            make_float4(acc0[0], acc0[1], acc0[2], acc0[3]);
        *reinterpret_cast<float4*>(&Ps[r1][nw * 128 + tx * 4]) =
            make_float4(acc1[0], acc1[1], acc1[2], acc1[3]);
    }
    __syncthreads();

    // ============ Phase B: stream codebook, on-the-fly norms, fused argmax ======
    float bv0 = -CUDART_INF_F, bv1 = -CUDART_INF_F;
    int   bi0 = 0,             bi1 = 0;

    for (int ct = 0; ct < CC / 128; ++ct) {          // 32 code tiles of 128
        const int c0 = ct * 128;
        float acc0[4] = {0.f, 0.f, 0.f, 0.f};
        float acc1[4] = {0.f, 0.f, 0.f, 0.f};
        float ss = 0.0f;                             // partial sum-of-squares (code tid>>1)

        for (int kt = 0; kt < EE / 8; ++kt) {        // 64 k-tiles of 8
            {                                        // C tile: 128 codes x 8 k
                const int cn = tid >> 1, ck = (tid & 1) * 4;
                float4 v = *reinterpret_cast<const float4*>(
                    CB + (size_t)(c0 + cn) * EE + kt * 8 + ck);
                Ts[ck + 0][cn] = v.x; Ts[ck + 1][cn] = v.y;
                Ts[ck + 2][cn] = v.z; Ts[ck + 3][cn] = v.w;
                ss = fmaf(v.x, v.x, ss); ss = fmaf(v.y, v.y, ss);
                ss = fmaf(v.z, v.z, ss); ss = fmaf(v.w, v.w, ss);
            }
            __syncthreads();

            #pragma unroll
            for (int kk = 0; kk < 8; ++kk) {
                const float a0 = Ps[r0][kt * 8 + kk];
                const float a1 = Ps[r1][kt * 8 + kk];
                float4 c = *reinterpret_cast<const float4*>(&Ts[kk][tx * 4]);
                acc0[0] = fmaf(a0, c.x, acc0[0]); acc0[1] = fmaf(a0, c.y, acc0[1]);
                acc0[2] = fmaf(a0, c.z, acc0[2]); acc0[3] = fmaf(a0, c.w, acc0[3]);
                acc1[0] = fmaf(a1, c.x, acc1[0]); acc1[1] = fmaf(a1, c.y, acc1[1]);
                acc1[2] = fmaf(a1, c.z, acc1[2]); acc1[3] = fmaf(a1, c.w, acc1[3]);
            }
            __syncthreads();
        }

        // finalize inverse norms for this tile: threads (2k, 2k+1) share code k
        ss += __shfl_xor_sync(0xffffffffu, ss, 1);
        if ((tid & 1) == 0)
            inv_s[tid >> 1] = 1.0f / fmaxf(sqrtf(ss), 1e-12f);
        __syncthreads();

        // fold into running argmax: n ascends, strict > keeps lowest index on ties
        #pragma unroll
        for (int j = 0; j < 4; j++) {
            const float inv = inv_s[tx * 4 + j];
            const int   n   = c0 + tx * 4 + j;
            const float v0  = acc0[j] * inv;
            const float v1  = acc1[j] * inv;
            if (v0 > bv0) { bv0 = v0; bi0 = n; }
            if (v1 > bv1) { bv1 = v1; bi1 = n; }
        }
        __syncthreads();   // inv_s stable until every thread has folded
    }

    // ============ warp-level argmax reduction (warp == ty, 32 lanes) ============
    #pragma unroll
    for (int o = 16; o > 0; o >>= 1) {
        float ov0 = __shfl_xor_sync(0xffffffffu, bv0, o);
        int   oi0 = __shfl_xor_sync(0xffffffffu, bi0, o);
        float ov1 = __shfl_xor_sync(0xffffffffu, bv1, o);
        int   oi1 = __shfl_xor_sync(0xffffffffu, bi1, o);
        if (ov0 > bv0 || (ov0 == bv0 && oi0 < bi0)) { bv0 = ov0; bi0 = oi0; }
        if (ov1 > bv1 || (ov1 == bv1 && oi1 < bi1)) { bv1 = ov1; bi1 = oi1; }
    }
    if (tx == 0) {
        out[m0 + r0] = (float)bi0;   // output dtype: float32 (indices exact in fp32)
        out[m0 + r1] = (float)bi1;
    }
}

// ---------------- launch ----------------
extern "C" void kernel_launch(void* const* d_in, const int* in_sizes, int n_in,
                              void* d_out, int out_size) {
    // Positional default per metadata order: x, random_projection, codebook.
    const float* x  = (const float*)d_in[0];
    const float* rp = (n_in > 1) ? (const float*)d_in[1] : (const float*)d_in[0];
    const float* cb = (n_in > 2) ? (const float*)d_in[2] : (const float*)d_in[0];

    // Robust re-identification: try "in_sizes are ELEMENT counts" first, then
    // "in_sizes are BYTE counts". (CC*EE == 4*DD*EE, so the two interpretations
    // must not be mixed.) Fall back to positional if neither fits all three.
    const long long wantE[3] = { (long long)BN * DD, (long long)DD * EE,
                                 (long long)CC * EE };
    for (int scale = 1; scale <= 4; scale *= 4) {   // 1 = elements, 4 = bytes
        const float* m[3] = { nullptr, nullptr, nullptr };
        for (int w = 0; w < 3; w++)
            for (int i = 0; i < n_in && i < 8; i++)
                if ((long long)in_sizes[i] == wantE[w] * scale && !m[w])
                    m[w] = (const float*)d_in[i];
        if (m[0] && m[1] && m[2]) { x = m[0]; rp = m[1]; cb = m[2]; break; }
    }

    rpq_all<<<BN / TM, 256>>>(x, rp, cb, (float*)d_out);   // 2048 blocks, 1 launch
}

// round 12
// speedup vs baseline: 2.0245x; 2.0245x over previous
#include <cuda_runtime.h>
#include <cstdint>

// Problem shape
#define BN   32768   // B*N rows
#define DD   1024    // input dim
#define EE   512     // projection dim
#define CC   4096    // codebook size

#define MT 128
#define NT 128
#define KT 8

// Scratch (device globals: allocation-free per harness rules)
__device__ __align__(16) float g_proj[BN * EE];   // 64 MB
__device__ __align__(16) float g_cn[CC * EE];     // 8 MB

// ---------------- packed f32x2 helpers ----------------
__device__ __forceinline__ unsigned long long pk2(float lo, float hi) {
    unsigned long long r;
    asm("mov.b64 %0, {%1, %2};" : "=l"(r) : "f"(lo), "f"(hi));
    return r;
}
__device__ __forceinline__ void upk2(unsigned long long v, float& lo, float& hi) {
    asm("mov.b64 {%0, %1}, %2;" : "=f"(lo), "=f"(hi) : "l"(v));
}
__device__ __forceinline__ unsigned long long ffma2(unsigned long long a,
                                                    unsigned long long b,
                                                    unsigned long long c) {
    unsigned long long d;
    asm("fma.rn.f32x2 %0, %1, %2, %3;" : "=l"(d) : "l"(a), "l"(b), "l"(c));
    return d;
}

// Monotonic float->uint key packing (value, 4095-idx): max() picks highest value,
// ties resolve to the LOWEST index (jnp.argmax rule). All keys > 0.
__device__ __forceinline__ unsigned long long packkey(float v, int n) {
    unsigned u = __float_as_uint(v);
    u = (u & 0x80000000u) ? ~u : (u | 0x80000000u);
    return ((unsigned long long)u << 32) | (unsigned)(4095 - n);
}

// ---------------- K0: normalize codebook rows ----------------
__global__ void normalize_codebook(const float* __restrict__ cb) {
    const int row = blockIdx.x;      // 4096
    const int tid = threadIdx.x;     // 128
    float4 v = reinterpret_cast<const float4*>(cb + (size_t)row * EE)[tid];
    float s = v.x * v.x + v.y * v.y + v.z * v.z + v.w * v.w;
    #pragma unroll
    for (int o = 16; o > 0; o >>= 1) s += __shfl_xor_sync(0xffffffffu, s, o);
    __shared__ float ws[4];
    if ((tid & 31) == 0) ws[tid >> 5] = s;
    __syncthreads();
    const float total = ws[0] + ws[1] + ws[2] + ws[3];
    const float inv = 1.0f / fmaxf(sqrtf(total), 1e-12f);
    float4 o4 = make_float4(v.x * inv, v.y * inv, v.z * inv, v.w * inv);
    reinterpret_cast<float4*>(g_cn + (size_t)row * EE)[tid] = o4;
}

// ---------------- K1: P = X @ W  (NN, fp32, FFMA2, double-buffered) ----------------
__global__ __launch_bounds__(256, 2)
void proj_gemm(const float* __restrict__ X, const float* __restrict__ W) {
    __shared__ __align__(16) float As[2][KT][MT];
    __shared__ __align__(16) float Bs[2][KT][NT];

    const int tid = threadIdx.x;
    const int m0 = blockIdx.y * MT;
    const int n0 = blockIdx.x * NT;
    const int tx = tid & 15, ty = tid >> 4;

    const int am = tid >> 1,  ak = (tid & 1) * 4;    // A tile: 128m x 8k
    const int bk = tid >> 5,  be = (tid & 31) * 4;   // B tile: 8k x 128n

    const float* aptr = X + (size_t)(m0 + am) * DD + ak;
    const float* bptr = W + (size_t)bk * EE + n0 + be;

    unsigned long long acc2[4][8];
    #pragma unroll
    for (int i = 0; i < 4; i++)
        #pragma unroll
        for (int j = 0; j < 8; j++) acc2[i][j] = 0ULL;

    float4 pa = *reinterpret_cast<const float4*>(aptr);
    float4 pb = *reinterpret_cast<const float4*>(bptr);
    As[0][ak + 0][am] = pa.x; As[0][ak + 1][am] = pa.y;
    As[0][ak + 2][am] = pa.z; As[0][ak + 3][am] = pa.w;
    *reinterpret_cast<float4*>(&Bs[0][bk][be]) = pb;
    __syncthreads();

    const int T = DD / KT;  // 128
    for (int kt = 0; kt < T; ++kt) {
        const int s = kt & 1;
        if (kt + 1 < T) {
            pa = *reinterpret_cast<const float4*>(aptr + (kt + 1) * KT);
            pb = *reinterpret_cast<const float4*>(bptr + (size_t)(kt + 1) * KT * EE);
        }
        #pragma unroll
        for (int kk = 0; kk < KT; ++kk) {
            ulonglong2 a01 = *reinterpret_cast<const ulonglong2*>(&As[s][kk][ty * 8]);
            ulonglong2 a23 = *reinterpret_cast<const ulonglong2*>(&As[s][kk][ty * 8 + 4]);
            float4 b0 = *reinterpret_cast<const float4*>(&Bs[s][kk][tx * 8]);
            float4 b1 = *reinterpret_cast<const float4*>(&Bs[s][kk][tx * 8 + 4]);
            unsigned long long a2[4] = {a01.x, a01.y, a23.x, a23.y};
            unsigned long long bb[8];
            bb[0] = pk2(b0.x, b0.x); bb[1] = pk2(b0.y, b0.y);
            bb[2] = pk2(b0.z, b0.z); bb[3] = pk2(b0.w, b0.w);
            bb[4] = pk2(b1.x, b1.x); bb[5] = pk2(b1.y, b1.y);
            bb[6] = pk2(b1.z, b1.z); bb[7] = pk2(b1.w, b1.w);
            #pragma unroll
            for (int ip = 0; ip < 4; ip++)
                #pragma unroll
                for (int j = 0; j < 8; j++)
                    acc2[ip][j] = ffma2(a2[ip], bb[j], acc2[ip][j]);
        }
        if (kt + 1 < T) {
            const int ns = s ^ 1;
            As[ns][ak + 0][am] = pa.x; As[ns][ak + 1][am] = pa.y;
            As[ns][ak + 2][am] = pa.z; As[ns][ak + 3][am] = pa.w;
            *reinterpret_cast<float4*>(&Bs[ns][bk][be]) = pb;
        }
        __syncthreads();
    }

    // epilogue: accumulator pairs are rows (2ip, 2ip+1) within this thread's 8 rows
    #pragma unroll
    for (int ip = 0; ip < 4; ip++) {
        float lo[8], hi[8];
        #pragma unroll
        for (int j = 0; j < 8; j++) upk2(acc2[ip][j], lo[j], hi[j]);
        const int mlo = m0 + ty * 8 + 2 * ip;
        float* out0 = g_proj + (size_t)mlo * EE + n0 + tx * 8;
        float* out1 = out0 + EE;
        *reinterpret_cast<float4*>(out0)     = make_float4(lo[0], lo[1], lo[2], lo[3]);
        *reinterpret_cast<float4*>(out0 + 4) = make_float4(lo[4], lo[5], lo[6], lo[7]);
        *reinterpret_cast<float4*>(out1)     = make_float4(hi[0], hi[1], hi[2], hi[3]);
        *reinterpret_cast<float4*>(out1 + 4) = make_float4(hi[4], hi[5], hi[6], hi[7]);
    }
}

// ---------------- K2: S = P @ Cn^T + fused row argmax ----------------
__global__ __launch_bounds__(256, 2)
void sim_argmax(float* __restrict__ out) {
    __shared__ __align__(16) float As[2][KT][MT];
    __shared__ __align__(16) float Bs[2][KT][NT];
    __shared__ unsigned long long red[MT][17];   // padded: conflict-free

    const int tid = threadIdx.x;
    const int m0 = blockIdx.x * MT;
    const int tx = tid & 15, ty = tid >> 4;

    const int am = tid >> 1, ak  = (tid & 1) * 4;   // A tile: 128m x 8k
    const int bn = tid >> 1, bkq = (tid & 1) * 4;   // B tile: 128n(codes) x 8k

    const float* aptr = g_proj + (size_t)(m0 + am) * EE + ak;

    unsigned long long best[8];
    #pragma unroll
    for (int i = 0; i < 8; i++) best[i] = 0ULL;

    for (int nt = 0; nt < CC / NT; ++nt) {
        const int n0 = nt * NT;
        const float* bptr = g_cn + (size_t)(n0 + bn) * EE + bkq;

        unsigned long long acc2[4][8];
        #pragma unroll
        for (int i = 0; i < 4; i++)
            #pragma unroll
            for (int j = 0; j < 8; j++) acc2[i][j] = 0ULL;

        float4 pa = *reinterpret_cast<const float4*>(aptr);
        float4 pb = *reinterpret_cast<const float4*>(bptr);
        As[0][ak + 0][am] = pa.x; As[0][ak + 1][am] = pa.y;
        As[0][ak + 2][am] = pa.z; As[0][ak + 3][am] = pa.w;
        Bs[0][bkq + 0][bn] = pb.x; Bs[0][bkq + 1][bn] = pb.y;
        Bs[0][bkq + 2][bn] = pb.z; Bs[0][bkq + 3][bn] = pb.w;
        __syncthreads();

        const int T = EE / KT;  // 64
        for (int kt = 0; kt < T; ++kt) {
            const int s = kt & 1;
            if (kt + 1 < T) {
                pa = *reinterpret_cast<const float4*>(aptr + (kt + 1) * KT);
                pb = *reinterpret_cast<const float4*>(bptr + (kt + 1) * KT);
            }
            #pragma unroll
            for (int kk = 0; kk < KT; ++kk) {
                ulonglong2 a01 = *reinterpret_cast<const ulonglong2*>(&As[s][kk][ty * 8]);
                ulonglong2 a23 = *reinterpret_cast<const ulonglong2*>(&As[s][kk][ty * 8 + 4]);
                float4 b0 = *reinterpret_cast<const float4*>(&Bs[s][kk][tx * 8]);
                float4 b1 = *reinterpret_cast<const float4*>(&Bs[s][kk][tx * 8 + 4]);
                unsigned long long a2[4] = {a01.x, a01.y, a23.x, a23.y};
                unsigned long long bb[8];
                bb[0] = pk2(b0.x, b0.x); bb[1] = pk2(b0.y, b0.y);
                bb[2] = pk2(b0.z, b0.z); bb[3] = pk2(b0.w, b0.w);
                bb[4] = pk2(b1.x, b1.x); bb[5] = pk2(b1.y, b1.y);
                bb[6] = pk2(b1.z, b1.z); bb[7] = pk2(b1.w, b1.w);
                #pragma unroll
                for (int ip = 0; ip < 4; ip++)
                    #pragma unroll
                    for (int j = 0; j < 8; j++)
                        acc2[ip][j] = ffma2(a2[ip], bb[j], acc2[ip][j]);
            }
            if (kt + 1 < T) {
                const int ns = s ^ 1;
                As[ns][ak + 0][am] = pa.x; As[ns][ak + 1][am] = pa.y;
                As[ns][ak + 2][am] = pa.z; As[ns][ak + 3][am] = pa.w;
                Bs[ns][bkq + 0][bn] = pb.x; Bs[ns][bkq + 1][bn] = pb.y;
                Bs[ns][bkq + 2][bn] = pb.z; Bs[ns][bkq + 3][bn] = pb.w;
            }
            __syncthreads();
        }

        // fold this N-tile into running per-row argmax keys
        #pragma unroll
        for (int ip = 0; ip < 4; ip++) {
            #pragma unroll
            for (int j = 0; j < 8; j++) {
                float lo, hi;
                upk2(acc2[ip][j], lo, hi);
                const int n = n0 + tx * 8 + j;
                unsigned long long klo = packkey(lo, n);
                unsigned long long khi = packkey(hi, n);
                if (klo > best[2 * ip])     best[2 * ip]     = klo;
                if (khi > best[2 * ip + 1]) best[2 * ip + 1] = khi;
            }
        }
    }

    // cross-thread (tx) reduction per row
    #pragma unroll
    for (int i = 0; i < 8; i++) red[ty * 8 + i][tx] = best[i];
    __syncthreads();
    if (tid < MT) {
        unsigned long long b = red[tid][0];
        #pragma unroll
        for (int t = 1; t < 16; t++) {
            unsigned long long v = red[tid][t];
            if (v > b) b = v;
        }
        // output dtype: FLOAT32 (indices < 2^24 exact) — the R11 lesson.
        out[m0 + tid] = (float)(4095 - (int)(unsigned)(b & 0xFFFFFFFFu));
    }
}

// ---------------- launch ----------------
extern "C" void kernel_launch(void* const* d_in, const int* in_sizes, int n_in,
                              void* d_out, int out_size) {
    // Positional default per metadata order: x, random_projection, codebook.
    const float* x  = (const float*)d_in[0];
    const float* rp = (n_in > 1) ? (const float*)d_in[1] : (const float*)d_in[0];
    const float* cb = (n_in > 2) ? (const float*)d_in[2] : (const float*)d_in[0];

    // Robust re-identification (elements first, then bytes; never mixed).
    const long long wantE[3] = { (long long)BN * DD, (long long)DD * EE,
                                 (long long)CC * EE };
    for (int scale = 1; scale <= 4; scale *= 4) {
        const float* m[3] = { nullptr, nullptr, nullptr };
        for (int w = 0; w < 3; w++)
            for (int i = 0; i < n_in && i < 8; i++)
                if ((long long)in_sizes[i] == wantE[w] * scale && !m[w])
                    m[w] = (const float*)d_in[i];
        if (m[0] && m[1] && m[2]) { x = m[0]; rp = m[1]; cb = m[2]; break; }
    }

    normalize_codebook<<<CC, 128>>>(cb);
    proj_gemm<<<dim3(EE / NT, BN / MT), 256>>>(x, rp);   // (4, 256)
    sim_argmax<<<BN / MT, 256>>>((float*)d_out);         // 256 blocks
}